// round 1
// baseline (speedup 1.0000x reference)
#include <cuda_runtime.h>

#define NN 8192
#define FF 128
#define EE 262144
#define METAL 64
#define NOUT 17
#define TWO_N (2*NN)
#define TWO_E (2*EE)
#define KSPLIT 64
#define KCHUNK (TWO_N / KSPLIT)   // 256

// ---- scratch (device globals: no allocation allowed) ----
__device__ float d_deg[TWO_N];
__device__ float d_dinv[TWO_N];
__device__ float d_g[TWO_N * 8];
__device__ float d_ya[TWO_N * 8];
__device__ float d_yb[TWO_N * 8];
__device__ float d_h[TWO_N];      // concat(h1, h2)
__device__ float d_res[NN];       // result_inter

// ---------------------------------------------------------------- degrees
__global__ void k_init_deg() {
    int i = blockIdx.x * blockDim.x + threadIdx.x;
    if (i < TWO_N) d_deg[i] = 1.0f;   // self-loop
}

__global__ void k_count(const int* __restrict__ ei1, const int* __restrict__ ei2) {
    int e = blockIdx.x * blockDim.x + threadIdx.x;
    if (e >= TWO_E) return;
    if (e < EE) atomicAdd(&d_deg[ei1[EE + e]], 1.0f);
    else        atomicAdd(&d_deg[NN + ei2[EE + (e - EE)]], 1.0f);
}

__global__ void k_dinv() {
    int i = blockIdx.x * blockDim.x + threadIdx.x;
    if (i < TWO_N) d_dinv[i] = rsqrtf(d_deg[i]);
}

// ------------------------------------------------- layer 1: g = dinv*(x@W1)
__global__ void k_gemm1(const float* __restrict__ x1,
                        const float* __restrict__ x2,
                        const float* __restrict__ W1) {
    int i = blockIdx.x * blockDim.x + threadIdx.x;
    if (i >= TWO_N) return;
    const float* x = (i < NN) ? (x1 + (size_t)i * FF) : (x2 + (size_t)(i - NN) * FF);
    const float4* x4 = (const float4*)x;
    float acc[8];
#pragma unroll
    for (int c = 0; c < 8; c++) acc[c] = 0.0f;
#pragma unroll 4
    for (int f4 = 0; f4 < FF / 4; f4++) {
        float4 v = x4[f4];
        float vv[4] = {v.x, v.y, v.z, v.w};
#pragma unroll
        for (int q = 0; q < 4; q++) {
            int f = f4 * 4 + q;
#pragma unroll
            for (int c = 0; c < 8; c++)
                acc[c] += vv[q] * __ldg(&W1[f * 8 + c]);
        }
    }
    float dv = d_dinv[i];
#pragma unroll
    for (int c = 0; c < 8; c++) {
        float g = dv * acc[c];
        d_g[i * 8 + c]  = g;
        d_ya[i * 8 + c] = g;   // self-loop init
    }
}

// ------------------------------------------------- edge scatter: y[dst]+=g[src]
template <int C>
__global__ void k_scatter(const int* __restrict__ ei1, const int* __restrict__ ei2,
                          int dst_sel) {
    int e = blockIdx.x * blockDim.x + threadIdx.x;
    if (e >= TWO_E) return;
    int s, d;
    if (e < EE) { s = ei1[e];            d = ei1[EE + e]; }
    else        { int ee = e - EE; s = NN + ei2[ee]; d = NN + ei2[EE + ee]; }
    float* y = dst_sel ? d_yb : d_ya;
#pragma unroll
    for (int c = 0; c < C; c++)
        atomicAdd(&y[d * C + c], d_g[s * C + c]);
}

// ---------------------------------- transform: z=dinv*y+b ; g'=dinv*(z@W)
template <int CIN, int COUT>
__global__ void k_transform(const float* __restrict__ b, const float* __restrict__ W,
                            int src_sel) {
    int i = blockIdx.x * blockDim.x + threadIdx.x;
    if (i >= TWO_N) return;
    const float* ys = src_sel ? d_yb : d_ya;
    float*       yd = src_sel ? d_ya : d_yb;
    float dv = d_dinv[i];
    float z[CIN];
#pragma unroll
    for (int c = 0; c < CIN; c++) z[c] = dv * ys[i * CIN + c] + __ldg(&b[c]);
#pragma unroll
    for (int cc = 0; cc < COUT; cc++) {
        float s = 0.0f;
#pragma unroll
        for (int c = 0; c < CIN; c++) s += z[c] * __ldg(&W[c * COUT + cc]);
        float g = dv * s;
        d_g[i * COUT + cc] = g;
        yd[i * COUT + cc]  = g;
    }
}

// ------------------------------------------------- branch output h = dinv*y + b4
__global__ void k_final(const float* __restrict__ b4, int src_sel) {
    int i = blockIdx.x * blockDim.x + threadIdx.x;
    if (i >= TWO_N) return;
    const float* ys = src_sel ? d_yb : d_ya;
    d_h[i] = d_dinv[i] * ys[i] + __ldg(&b4[0]);
}

// ------------------------------------------------- result_inter = bi (init)
__global__ void k_res_init(const float* __restrict__ bi) {
    int i = blockIdx.x * blockDim.x + threadIdx.x;
    if (i < NN) d_res[i] = bi[i];
}

// ---------------------- big GEMV: res[j] += sum_k h[k]*Wi[k*N+j]  (k-split)
__global__ void k_wi_gemv(const float* __restrict__ Wi) {
    int j4 = blockIdx.x * blockDim.x + threadIdx.x;   // 0..2047 (float4 columns)
    int k0 = blockIdx.y * KCHUNK;
    const float4* Wi4 = (const float4*)Wi;
    float4 acc = make_float4(0.f, 0.f, 0.f, 0.f);
#pragma unroll 4
    for (int kk = 0; kk < KCHUNK; kk++) {
        int k = k0 + kk;
        float c = d_h[k];
        float4 w = Wi4[(size_t)k * (NN / 4) + j4];
        acc.x += c * w.x; acc.y += c * w.y; acc.z += c * w.z; acc.w += c * w.w;
    }
    int j = j4 * 4;
    atomicAdd(&d_res[j + 0], acc.x);
    atomicAdd(&d_res[j + 1], acc.y);
    atomicAdd(&d_res[j + 2], acc.z);
    atomicAdd(&d_res[j + 3], acc.w);
}

// ------------------------------------------------- out init: bf + meta part
__global__ void k_out_init(const float* __restrict__ meta,
                           const float* __restrict__ Wf,
                           const float* __restrict__ bf,
                           float* __restrict__ out) {
    int j = threadIdx.x;
    if (j < NOUT) {
        float s = bf[j];
#pragma unroll 8
        for (int m = 0; m < METAL; m++)
            s += meta[m] * Wf[(size_t)(NN + m) * NOUT + j];
        out[j] = s;
    }
}

// ------------------------------------------------- out += res @ Wf[:N]
__global__ void k_out_acc(const float* __restrict__ Wf, float* __restrict__ out) {
    int i = blockIdx.x * blockDim.x + threadIdx.x;   // exactly NN threads
    float r = d_res[i];
    float acc[NOUT];
#pragma unroll
    for (int j = 0; j < NOUT; j++) acc[j] = r * Wf[(size_t)i * NOUT + j];
#pragma unroll
    for (int j = 0; j < NOUT; j++) {
#pragma unroll
        for (int o = 16; o > 0; o >>= 1)
            acc[j] += __shfl_xor_sync(0xffffffff, acc[j], o);
    }
    if ((threadIdx.x & 31) == 0) {
#pragma unroll
        for (int j = 0; j < NOUT; j++) atomicAdd(&out[j], acc[j]);
    }
}

// ================================================================= launch
extern "C" void kernel_launch(void* const* d_in, const int* in_sizes, int n_in,
                              void* d_out, int out_size) {
    const float* x1   = (const float*)d_in[0];
    const float* x2   = (const float*)d_in[1];
    const float* meta = (const float*)d_in[2];
    const float* W1   = (const float*)d_in[3];
    const float* b1   = (const float*)d_in[4];
    const float* W2   = (const float*)d_in[5];
    const float* b2   = (const float*)d_in[6];
    const float* W3   = (const float*)d_in[7];
    const float* b3   = (const float*)d_in[8];
    const float* W4   = (const float*)d_in[9];
    const float* b4   = (const float*)d_in[10];
    const float* Wi   = (const float*)d_in[11];
    const float* bi   = (const float*)d_in[12];
    const float* Wf   = (const float*)d_in[13];
    const float* bf   = (const float*)d_in[14];
    const int*   ei1  = (const int*)d_in[15];
    const int*   ei2  = (const int*)d_in[16];
    float* out = (float*)d_out;

    const int T = 256;
    // degrees + norm
    k_init_deg<<<TWO_N / T, T>>>();
    k_count<<<TWO_E / T, T>>>(ei1, ei2);
    k_dinv<<<TWO_N / T, T>>>();
    // layer 1 (F=128 -> 8)
    k_gemm1<<<TWO_N / T, T>>>(x1, x2, W1);
    k_scatter<8><<<TWO_E / T, T>>>(ei1, ei2, /*dst=*/0);   // into ya
    // layer 2 (8 -> 4)
    k_transform<8, 4><<<TWO_N / T, T>>>(b1, W2, /*src=*/0); // ya -> yb
    k_scatter<4><<<TWO_E / T, T>>>(ei1, ei2, /*dst=*/1);
    // layer 3 (4 -> 2)
    k_transform<4, 2><<<TWO_N / T, T>>>(b2, W3, /*src=*/1); // yb -> ya
    k_scatter<2><<<TWO_E / T, T>>>(ei1, ei2, /*dst=*/0);
    // layer 4 (2 -> 1)
    k_transform<2, 1><<<TWO_N / T, T>>>(b3, W4, /*src=*/0); // ya -> yb
    k_scatter<1><<<TWO_E / T, T>>>(ei1, ei2, /*dst=*/1);
    k_final<<<TWO_N / T, T>>>(b4, /*src=*/1);
    // inter dense: res = concat(h1,h2) @ Wi + bi
    k_res_init<<<NN / T, T>>>(bi);
    {
        dim3 grid(NN / (T * 4), KSPLIT);
        k_wi_gemv<<<grid, T>>>(Wi);
    }
    // final dense: out = concat(res, meta) @ Wf + bf
    k_out_init<<<1, 32>>>(meta, Wf, bf, out);
    k_out_acc<<<NN / T, T>>>(Wf, out);
}

// round 2
// speedup vs baseline: 1.4152x; 1.4152x over previous
#include <cuda_runtime.h>

#define NN 8192
#define FF 128
#define EE 262144
#define METAL 64
#define NOUT 17
#define TWO_N (2*NN)
#define TWO_E (2*EE)
#define KSPLIT 128
#define KCHUNK (TWO_N / KSPLIT)   // 128

// ---- scratch (device globals: no allocation allowed) ----
__device__ float d_deg[TWO_N];
__device__ float d_dinv[TWO_N];
__device__ float d_g[TWO_N];
__device__ float d_y[TWO_N];
__device__ float d_h[TWO_N];      // concat(h1, h2)
__device__ float d_res[NN];       // result_inter
__device__ float d_wc[FF];        // W1@W2@W3@W4
__device__ float d_c[4];          // c1, c2, c3, b4

// ---------------------------------------------------------------- degrees
__global__ void k_init_deg() {
    int i = blockIdx.x * blockDim.x + threadIdx.x;
    if (i < TWO_N) d_deg[i] = 1.0f;   // self-loop
}

__global__ void k_count(const int* __restrict__ ei1, const int* __restrict__ ei2) {
    int e = blockIdx.x * blockDim.x + threadIdx.x;
    if (e >= TWO_E) return;
    if (e < EE) atomicAdd(&d_deg[ei1[EE + e]], 1.0f);
    else        atomicAdd(&d_deg[NN + ei2[EE + (e - EE)]], 1.0f);
}

__global__ void k_dinv() {
    int i = blockIdx.x * blockDim.x + threadIdx.x;
    if (i < TWO_N) d_dinv[i] = rsqrtf(d_deg[i]);
}

// ------------------------------------------- combined weights (tiny kernel)
__global__ void k_combine(const float* __restrict__ W1, const float* __restrict__ b1,
                          const float* __restrict__ W2, const float* __restrict__ b2,
                          const float* __restrict__ W3, const float* __restrict__ b3,
                          const float* __restrict__ W4, const float* __restrict__ b4) {
    int f = threadIdx.x;     // 128 threads
    float w34[4], w234[8];
#pragma unroll
    for (int c = 0; c < 4; c++)
        w34[c] = W3[c * 2 + 0] * W4[0] + W3[c * 2 + 1] * W4[1];
#pragma unroll
    for (int r = 0; r < 8; r++) {
        float s = 0.0f;
#pragma unroll
        for (int c = 0; c < 4; c++) s += W2[r * 4 + c] * w34[c];
        w234[r] = s;
    }
    float s = 0.0f;
#pragma unroll
    for (int r = 0; r < 8; r++) s += W1[f * 8 + r] * w234[r];
    d_wc[f] = s;
    if (f == 0) {
        float c1 = 0.0f, c2 = 0.0f;
#pragma unroll
        for (int r = 0; r < 8; r++) c1 += b1[r] * w234[r];
#pragma unroll
        for (int c = 0; c < 4; c++) c2 += b2[c] * w34[c];
        d_c[0] = c1;
        d_c[1] = c2;
        d_c[2] = b3[0] * W4[0] + b3[1] * W4[1];
        d_c[3] = b4[0];
    }
}

// ----------------------- v = x @ wc ; g = dinv*v ; y = g  (warp per node)
__global__ void k_xwc(const float* __restrict__ x1, const float* __restrict__ x2) {
    __shared__ float swc[FF];
    if (threadIdx.x < FF) swc[threadIdx.x] = d_wc[threadIdx.x];
    __syncthreads();
    int gt = blockIdx.x * blockDim.x + threadIdx.x;
    int i = gt >> 5;
    int lane = gt & 31;
    if (i >= TWO_N) return;
    const float* x = (i < NN) ? (x1 + (size_t)i * FF) : (x2 + (size_t)(i - NN) * FF);
    float4 v = ((const float4*)x)[lane];
    float4 w = ((const float4*)swc)[lane];
    float s = v.x * w.x + v.y * w.y + v.z * w.z + v.w * w.w;
#pragma unroll
    for (int o = 16; o > 0; o >>= 1) s += __shfl_xor_sync(0xffffffff, s, o);
    if (lane == 0) {
        float g = d_dinv[i] * s;
        d_g[i] = g;
        d_y[i] = g;
    }
}

// ------------------------------------------------- scalar edge scatter
__global__ void k_scat(const int* __restrict__ ei1, const int* __restrict__ ei2) {
    int e = blockIdx.x * blockDim.x + threadIdx.x;
    if (e >= TWO_E) return;
    int s, d;
    if (e < EE) { s = ei1[e]; d = ei1[EE + e]; }
    else        { int ee = e - EE; s = NN + ei2[ee]; d = NN + ei2[EE + ee]; }
    atomicAdd(&d_y[d], d_g[s]);
}

// ------------------------ per-round node update: u = dinv*y + c[r]
__global__ void k_node(int r) {
    int i = blockIdx.x * blockDim.x + threadIdx.x;
    if (i >= TWO_N) return;
    float dv = d_dinv[i];
    float u = dv * d_y[i] + d_c[r];
    if (r < 3) {
        float g = dv * u;
        d_g[i] = g;
        d_y[i] = g;
    } else {
        d_h[i] = u;    // h = t4
    }
}

// ------------------------------------------------- result_inter = bi (init)
__global__ void k_res_init(const float* __restrict__ bi) {
    int i = blockIdx.x * blockDim.x + threadIdx.x;
    if (i < NN) d_res[i] = bi[i];
}

// ---------------------- big GEMV: res[j] += sum_k h[k]*Wi[k*N+j]  (k-split)
__global__ void k_wi_gemv(const float* __restrict__ Wi) {
    __shared__ float sh[KCHUNK];
    int k0 = blockIdx.y * KCHUNK;
    if (threadIdx.x < KCHUNK) sh[threadIdx.x] = d_h[k0 + threadIdx.x];
    __syncthreads();
    int j4 = blockIdx.x * blockDim.x + threadIdx.x;   // 0..2047 (float4 columns)
    const float4* Wi4 = (const float4*)Wi;
    float4 acc = make_float4(0.f, 0.f, 0.f, 0.f);
#pragma unroll 8
    for (int kk = 0; kk < KCHUNK; kk++) {
        float c = sh[kk];
        float4 w = __ldcs(&Wi4[(size_t)(k0 + kk) * (NN / 4) + j4]);
        acc.x += c * w.x; acc.y += c * w.y; acc.z += c * w.z; acc.w += c * w.w;
    }
    int j = j4 * 4;
    atomicAdd(&d_res[j + 0], acc.x);
    atomicAdd(&d_res[j + 1], acc.y);
    atomicAdd(&d_res[j + 2], acc.z);
    atomicAdd(&d_res[j + 3], acc.w);
}

// ------------------------------------------------- out init: bf + meta part
__global__ void k_out_init(const float* __restrict__ meta,
                           const float* __restrict__ Wf,
                           const float* __restrict__ bf,
                           float* __restrict__ out) {
    int j = threadIdx.x;
    if (j < NOUT) {
        float s = bf[j];
#pragma unroll 8
        for (int m = 0; m < METAL; m++)
            s += meta[m] * Wf[(size_t)(NN + m) * NOUT + j];
        out[j] = s;
    }
}

// ------------------------------------------------- out += res @ Wf[:N]
__global__ void k_out_acc(const float* __restrict__ Wf, float* __restrict__ out) {
    int i = blockIdx.x * blockDim.x + threadIdx.x;   // exactly NN threads
    float r = d_res[i];
    float acc[NOUT];
#pragma unroll
    for (int j = 0; j < NOUT; j++) acc[j] = r * Wf[(size_t)i * NOUT + j];
#pragma unroll
    for (int j = 0; j < NOUT; j++) {
#pragma unroll
        for (int o = 16; o > 0; o >>= 1)
            acc[j] += __shfl_xor_sync(0xffffffff, acc[j], o);
    }
    if ((threadIdx.x & 31) == 0) {
#pragma unroll
        for (int j = 0; j < NOUT; j++) atomicAdd(&out[j], acc[j]);
    }
}

// ================================================================= launch
extern "C" void kernel_launch(void* const* d_in, const int* in_sizes, int n_in,
                              void* d_out, int out_size) {
    const float* x1   = (const float*)d_in[0];
    const float* x2   = (const float*)d_in[1];
    const float* meta = (const float*)d_in[2];
    const float* W1   = (const float*)d_in[3];
    const float* b1   = (const float*)d_in[4];
    const float* W2   = (const float*)d_in[5];
    const float* b2   = (const float*)d_in[6];
    const float* W3   = (const float*)d_in[7];
    const float* b3   = (const float*)d_in[8];
    const float* W4   = (const float*)d_in[9];
    const float* b4   = (const float*)d_in[10];
    const float* Wi   = (const float*)d_in[11];
    const float* bi   = (const float*)d_in[12];
    const float* Wf   = (const float*)d_in[13];
    const float* bf   = (const float*)d_in[14];
    const int*   ei1  = (const int*)d_in[15];
    const int*   ei2  = (const int*)d_in[16];
    float* out = (float*)d_out;

    const int T = 256;
    // degrees + norm + combined weights
    k_init_deg<<<TWO_N / T, T>>>();
    k_count<<<TWO_E / T, T>>>(ei1, ei2);
    k_combine<<<1, 128>>>(W1, b1, W2, b2, W3, b3, W4, b4);
    k_dinv<<<TWO_N / T, T>>>();
    // v0 = x @ wc, pre-scaled
    k_xwc<<<(TWO_N * 32) / T, T>>>(x1, x2);
    // four scalar propagations: t_{r+1} = A t_r + c_r
    for (int r = 0; r < 4; r++) {
        k_scat<<<TWO_E / T, T>>>(ei1, ei2);
        k_node<<<TWO_N / T, T>>>(r);
    }
    // inter dense: res = concat(h1,h2) @ Wi + bi
    k_res_init<<<NN / T, T>>>(bi);
    {
        dim3 grid(NN / (T * 4), KSPLIT);
        k_wi_gemv<<<grid, T>>>(Wi);
    }
    // final dense: out = concat(res, meta) @ Wf + bf
    k_out_init<<<1, 32>>>(meta, Wf, bf, out);
    k_out_acc<<<NN / T, T>>>(Wf, out);
}

// round 3
// speedup vs baseline: 1.4904x; 1.0532x over previous
#include <cuda_runtime.h>

#define NN 8192
#define FF 128
#define EE 262144
#define METAL 64
#define NOUT 17
#define TWO_N (2*NN)
#define TWO_E (2*EE)
#define KSPLIT 128
#define KCHUNK (TWO_N / KSPLIT)   // 128

// ---- scratch (device globals: no allocation allowed) ----
__device__ float d_deg[TWO_N];
__device__ float d_dinv[TWO_N];
__device__ float d_g[TWO_N];
__device__ float d_y[TWO_N];
__device__ float d_res[NN];       // result_inter partial sums (zeroed in setup)
__device__ float d_wc[FF];        // W1@W2@W3@W4
__device__ float d_c[4];          // c1, c2, c3, b4

// --------------------------------- setup: deg=1, res=0, combined weights
__global__ void k_setup(const float* __restrict__ W1, const float* __restrict__ b1,
                        const float* __restrict__ W2, const float* __restrict__ b2,
                        const float* __restrict__ W3, const float* __restrict__ b3,
                        const float* __restrict__ W4, const float* __restrict__ b4) {
    int i = blockIdx.x * blockDim.x + threadIdx.x;
    if (i < TWO_N) d_deg[i] = 1.0f;   // self-loop
    if (i < NN)    d_res[i] = 0.0f;
    if (blockIdx.x == 0 && threadIdx.x < FF) {
        int f = threadIdx.x;
        float w34[4], w234[8];
#pragma unroll
        for (int c = 0; c < 4; c++)
            w34[c] = W3[c * 2 + 0] * W4[0] + W3[c * 2 + 1] * W4[1];
#pragma unroll
        for (int r = 0; r < 8; r++) {
            float s = 0.0f;
#pragma unroll
            for (int c = 0; c < 4; c++) s += W2[r * 4 + c] * w34[c];
            w234[r] = s;
        }
        float s = 0.0f;
#pragma unroll
        for (int r = 0; r < 8; r++) s += W1[f * 8 + r] * w234[r];
        d_wc[f] = s;
        if (f == 0) {
            float c1 = 0.0f, c2 = 0.0f;
#pragma unroll
            for (int r = 0; r < 8; r++) c1 += b1[r] * w234[r];
#pragma unroll
            for (int c = 0; c < 4; c++) c2 += b2[c] * w34[c];
            d_c[0] = c1;
            d_c[1] = c2;
            d_c[2] = b3[0] * W4[0] + b3[1] * W4[1];
            d_c[3] = b4[0];
        }
    }
}

// ---------------------------------------------- degree count (4 edges/thread)
__global__ void k_count(const int* __restrict__ ei1, const int* __restrict__ ei2) {
    int t = blockIdx.x * blockDim.x + threadIdx.x;
    const int Q = EE / 4;
    int4 d;
    int off;
    if (t < Q) { d = ((const int4*)(ei1 + EE))[t];      off = 0; }
    else       { d = ((const int4*)(ei2 + EE))[t - Q];  off = NN; }
    atomicAdd(&d_deg[off + d.x], 1.0f);
    atomicAdd(&d_deg[off + d.y], 1.0f);
    atomicAdd(&d_deg[off + d.z], 1.0f);
    atomicAdd(&d_deg[off + d.w], 1.0f);
}

// ----------- dinv = rsqrt(deg); g = dinv*(x@wc); y = g   (warp per node)
__global__ void k_xwc(const float* __restrict__ x1, const float* __restrict__ x2) {
    __shared__ float swc[FF];
    if (threadIdx.x < FF) swc[threadIdx.x] = d_wc[threadIdx.x];
    __syncthreads();
    int gt = blockIdx.x * blockDim.x + threadIdx.x;
    int i = gt >> 5;
    int lane = gt & 31;
    if (i >= TWO_N) return;
    const float* x = (i < NN) ? (x1 + (size_t)i * FF) : (x2 + (size_t)(i - NN) * FF);
    float4 v = ((const float4*)x)[lane];
    float4 w = ((const float4*)swc)[lane];
    float s = v.x * w.x + v.y * w.y + v.z * w.z + v.w * w.w;
#pragma unroll
    for (int o = 16; o > 0; o >>= 1) s += __shfl_xor_sync(0xffffffff, s, o);
    if (lane == 0) {
        float dv = rsqrtf(d_deg[i]);
        d_dinv[i] = dv;
        float g = dv * s;
        d_g[i] = g;
        d_y[i] = g;
    }
}

// ---------------------------------- scalar edge scatter (4 edges/thread)
__global__ void k_scat(const int* __restrict__ ei1, const int* __restrict__ ei2) {
    int t = blockIdx.x * blockDim.x + threadIdx.x;
    const int Q = EE / 4;
    int4 s4, d4;
    int off;
    if (t < Q) {
        s4 = ((const int4*)ei1)[t];           d4 = ((const int4*)(ei1 + EE))[t];      off = 0;
    } else {
        s4 = ((const int4*)ei2)[t - Q];       d4 = ((const int4*)(ei2 + EE))[t - Q];  off = NN;
    }
    float g0 = d_g[off + s4.x];
    float g1 = d_g[off + s4.y];
    float g2 = d_g[off + s4.z];
    float g3 = d_g[off + s4.w];
    atomicAdd(&d_y[off + d4.x], g0);
    atomicAdd(&d_y[off + d4.y], g1);
    atomicAdd(&d_y[off + d4.z], g2);
    atomicAdd(&d_y[off + d4.w], g3);
}

// -------------------- node update rounds 0..2: g' = dinv*(dinv*y + c[r])
__global__ void k_node(int r) {
    int i = blockIdx.x * blockDim.x + threadIdx.x;
    if (i >= TWO_N) return;
    float dv = d_dinv[i];
    float g = dv * (dv * d_y[i] + d_c[r]);
    d_g[i] = g;
    d_y[i] = g;
}

// ---- big GEMV: res[j] += sum_k h[k]*Wi[k*N+j]; h computed on the fly.
//      block (0,0) also initializes out = bf + meta @ Wf[N:]
__global__ void k_wi_gemv(const float* __restrict__ Wi,
                          const float* __restrict__ meta,
                          const float* __restrict__ Wf,
                          const float* __restrict__ bf,
                          float* __restrict__ out) {
    __shared__ float sh[KCHUNK];
    int k0 = blockIdx.y * KCHUNK;
    if (threadIdx.x < KCHUNK) {
        int k = k0 + threadIdx.x;
        sh[threadIdx.x] = d_dinv[k] * d_y[k] + d_c[3];   // h = dinv*y + b4'
    }
    __syncthreads();
    int j4 = blockIdx.x * blockDim.x + threadIdx.x;   // float4 column index
    const float4* Wi4 = (const float4*)Wi;
    float4 acc = make_float4(0.f, 0.f, 0.f, 0.f);
#pragma unroll 8
    for (int kk = 0; kk < KCHUNK; kk++) {
        float c = sh[kk];
        float4 w = __ldcs(&Wi4[(size_t)(k0 + kk) * (NN / 4) + j4]);
        acc.x += c * w.x; acc.y += c * w.y; acc.z += c * w.z; acc.w += c * w.w;
    }
    int j = j4 * 4;
    atomicAdd(&d_res[j + 0], acc.x);
    atomicAdd(&d_res[j + 1], acc.y);
    atomicAdd(&d_res[j + 2], acc.z);
    atomicAdd(&d_res[j + 3], acc.w);
    // out init: runs before k_out_acc is launched (stream order), safe.
    if (blockIdx.x == 0 && blockIdx.y == 0 && threadIdx.x < NOUT) {
        int jj = threadIdx.x;
        float s = bf[jj];
#pragma unroll 8
        for (int m = 0; m < METAL; m++)
            s += meta[m] * Wf[(size_t)(NN + m) * NOUT + jj];
        out[jj] = s;
    }
}

// ---------------- out += (res + bi) @ Wf[:N]   (bi folded here)
__global__ void k_out_acc(const float* __restrict__ Wf,
                          const float* __restrict__ bi,
                          float* __restrict__ out) {
    int i = blockIdx.x * blockDim.x + threadIdx.x;   // exactly NN threads
    float r = d_res[i] + bi[i];
    float acc[NOUT];
#pragma unroll
    for (int j = 0; j < NOUT; j++) acc[j] = r * Wf[(size_t)i * NOUT + j];
#pragma unroll
    for (int j = 0; j < NOUT; j++) {
#pragma unroll
        for (int o = 16; o > 0; o >>= 1)
            acc[j] += __shfl_xor_sync(0xffffffff, acc[j], o);
    }
    if ((threadIdx.x & 31) == 0) {
#pragma unroll
        for (int j = 0; j < NOUT; j++) atomicAdd(&out[j], acc[j]);
    }
}

// ================================================================= launch
extern "C" void kernel_launch(void* const* d_in, const int* in_sizes, int n_in,
                              void* d_out, int out_size) {
    const float* x1   = (const float*)d_in[0];
    const float* x2   = (const float*)d_in[1];
    const float* meta = (const float*)d_in[2];
    const float* W1   = (const float*)d_in[3];
    const float* b1   = (const float*)d_in[4];
    const float* W2   = (const float*)d_in[5];
    const float* b2   = (const float*)d_in[6];
    const float* W3   = (const float*)d_in[7];
    const float* b3   = (const float*)d_in[8];
    const float* W4   = (const float*)d_in[9];
    const float* b4   = (const float*)d_in[10];
    const float* Wi   = (const float*)d_in[11];
    const float* bi   = (const float*)d_in[12];
    const float* Wf   = (const float*)d_in[13];
    const float* bf   = (const float*)d_in[14];
    const int*   ei1  = (const int*)d_in[15];
    const int*   ei2  = (const int*)d_in[16];
    float* out = (float*)d_out;

    const int T = 256;
    k_setup<<<TWO_N / T, T>>>(W1, b1, W2, b2, W3, b3, W4, b4);
    k_count<<<(TWO_E / 4) / T, T>>>(ei1, ei2);
    k_xwc<<<(TWO_N * 32) / T, T>>>(x1, x2);
    // four scalar propagations (last node-update folded into GEMV)
    for (int r = 0; r < 4; r++) {
        k_scat<<<(TWO_E / 4) / T, T>>>(ei1, ei2);
        if (r < 3) k_node<<<TWO_N / T, T>>>(r);
    }
    // res = h @ Wi (k-split, atomics); also inits out with bf + meta part
    {
        dim3 grid(NN / (T * 4), KSPLIT);
        k_wi_gemv<<<grid, T>>>(Wi, meta, Wf, bf, out);
    }
    // out += (res + bi) @ Wf[:N]
    k_out_acc<<<NN / T, T>>>(Wf, bi, out);
}